// round 14
// baseline (speedup 1.0000x reference)
#include <cuda_runtime.h>
#include <cuda_bf16.h>
#include <cstdint>

#define MASK_ID 50264
#define Bb 16
#define Ss 2048
#define Hh 1024
#define Ll 128
#define Mm (Bb*Ll)      // 2048
#define NBLK 8          // GEMM column blocks
#define XPB 128         // xproj blocks

// ---------------- device scratch ----------------
__device__ int   g_maskpos[Bb];
__device__ int   g_off[Ll];
__device__ float g_x[Bb*Hh];
__device__ float g_xT[Hh*Bb];
__device__ float g_z[Bb*Hh];
__device__ float g_xnp[XPB][Bb];
__device__ float g_xbp[XPB][Bb];
__device__ float g_dot[Mm];
__device__ float g_nnp[NBLK][Mm];

// ---------------- kernel 1: prep (17 blocks): offsets + per-batch mask scan ----------------
__global__ void prep_kernel(const int* __restrict__ ids_w, const int* __restrict__ off_w) {
    __shared__ int s_flag;
    __shared__ int s_min[256];
    int blk = blockIdx.x, t = threadIdx.x;
    if (t == 0) s_flag = 0;
    __syncthreads();
    int nz = 0;
    for (int i = t; i < 2048; i += 256) nz |= ids_w[2 * i + 1];
    if (nz) atomicOr(&s_flag, 1);
    __syncthreads();
    const bool is64 = (s_flag == 0);
    if (blk == Bb) {
        if (t < Ll) g_off[t] = is64 ? (int)((const long long*)off_w)[t] : off_w[t];
        return;
    }
    int b = blk;
    const long long* ids64 = (const long long*)ids_w;
    int mi = 0x7fffffff;
    for (int s = t; s < Ss; s += 256) {
        long long v = is64 ? ids64[(size_t)b * Ss + s] : (long long)ids_w[b * Ss + s];
        if (v == MASK_ID && s < mi) mi = s;
    }
    s_min[t] = mi;
    __syncthreads();
    for (int w = 128; w > 0; w >>= 1) {
        if (t < w) s_min[t] = min(s_min[t], s_min[t + w]);
        __syncthreads();
    }
    if (t == 0) g_maskpos[b] = (s_min[0] == 0x7fffffff) ? 0 : s_min[0];
}

// ---------------- kernel 2: x projection, W read once (grid 128, 256 thr) ----------------
__global__ void xproj_kernel(const float* __restrict__ q, const float* __restrict__ Wm,
                             const float* __restrict__ bias) {
    extern __shared__ __align__(16) float sq[];      // 64 KB
    __shared__ float sxn[8][Bb], sxb[8][Bb];
    int oc = blockIdx.x, t = threadIdx.x, wid = t >> 5, lane = t & 31;
    #pragma unroll
    for (int i = 0; i < 16; i++) {
        int idx = t + i * 256;
        int b = idx >> 8, h4 = idx & 255;
        ((float4*)sq)[idx] = *(const float4*)(q + ((size_t)b * Ss + g_maskpos[b]) * Hh + h4 * 4);
    }
    __syncthreads();
    int o = oc * 8 + wid;
    const float* wr = Wm + (size_t)o * Hh;
    float acc[Bb];
    #pragma unroll
    for (int b = 0; b < Bb; b++) acc[b] = 0.f;
    #pragma unroll
    for (int j = 0; j < 8; j++) {
        int h0 = j * 128 + lane * 4;
        float4 w4 = *(const float4*)(wr + h0);
        #pragma unroll
        for (int b = 0; b < Bb; b++) {
            float4 qv = *(const float4*)(sq + b * Hh + h0);
            acc[b] += w4.x * qv.x + w4.y * qv.y + w4.z * qv.z + w4.w * qv.w;
        }
    }
    #pragma unroll
    for (int b = 0; b < Bb; b++)
        #pragma unroll
        for (int d = 16; d > 0; d >>= 1)
            acc[b] += __shfl_xor_sync(0xffffffffu, acc[b], d);
    if (lane == 0) {
        float bo = bias[o];
        #pragma unroll
        for (int b = 0; b < Bb; b++) {
            float v = acc[b] + bo;
            g_x[b * Hh + o] = v;
            g_xT[o * Bb + b] = v;
            sxn[wid][b] = v * v;
            sxb[wid][b] = v * bo;
        }
    }
    __syncthreads();
    if (t < Bb) {
        float xn = 0.f, xb = 0.f;
        #pragma unroll
        for (int w = 0; w < 8; w++) { xn += sxn[w][t]; xb += sxb[w][t]; }
        g_xnp[oc][t] = xn;
        g_xbp[oc][t] = xb;
    }
}

// ---------------- kernel 3: z = W^T x (grid 64, 256 thr) ----------------
__global__ void zcomp_kernel(const float* __restrict__ Wm) {
    extern __shared__ __align__(16) float sxT[];     // 64 KB
    __shared__ float spz[16][Bb][16];
    int t = threadIdx.x;
    int hl = t & 15, och = t >> 4;
    int h = blockIdx.x * 16 + hl;
    #pragma unroll
    for (int i = 0; i < 16; i++) {
        int idx = t + i * 256;
        ((float4*)sxT)[idx] = ((const float4*)g_xT)[idx];
    }
    __syncthreads();
    float acc[Bb];
    #pragma unroll
    for (int b = 0; b < Bb; b++) acc[b] = 0.f;
    const float* wp = Wm + (size_t)(och * 64) * Hh + h;
    #pragma unroll 4
    for (int oi = 0; oi < 64; oi++) {
        float w = wp[(size_t)oi * Hh];
        const float4* xv = (const float4*)(sxT + (och * 64 + oi) * Bb);
        float4 x0 = xv[0], x1 = xv[1], x2 = xv[2], x3 = xv[3];
        acc[0]  += x0.x * w;  acc[1]  += x0.y * w;  acc[2]  += x0.z * w;  acc[3]  += x0.w * w;
        acc[4]  += x1.x * w;  acc[5]  += x1.y * w;  acc[6]  += x1.z * w;  acc[7]  += x1.w * w;
        acc[8]  += x2.x * w;  acc[9]  += x2.y * w;  acc[10] += x2.z * w;  acc[11] += x2.w * w;
        acc[12] += x3.x * w;  acc[13] += x3.y * w;  acc[14] += x3.z * w;  acc[15] += x3.w * w;
    }
    #pragma unroll
    for (int b = 0; b < Bb; b++) spz[och][b][hl] = acc[b];
    __syncthreads();
    int b = t >> 4, hl2 = t & 15;
    float z = 0.f;
    #pragma unroll
    for (int c = 0; c < 16; c++) z += spz[c][b][hl2];
    g_z[b * Hh + blockIdx.x * 16 + hl2] = z;
}

// ---------------- kernel 4: bf16 HMMA GEMM + fused exact dot (x-block 0 only) ----------------
#define GM 128
#define GN 128
#define GK 32
#define NC (Hh / GK)
#define SP 40
#define AHI 0
#define BHI (128*SP)
#define BUFS (2*128*SP)
#define SMEM_BYTES (2*BUFS*2)   // 40960 B

__device__ __forceinline__ void mma16816(float* d, const uint32_t* a, const uint32_t* b) {
    asm volatile("mma.sync.aligned.m16n8k16.row.col.f32.bf16.bf16.f32 "
                 "{%0,%1,%2,%3},{%4,%5,%6,%7},{%8,%9},{%0,%1,%2,%3};"
                 : "+f"(d[0]), "+f"(d[1]), "+f"(d[2]), "+f"(d[3])
                 : "r"(a[0]), "r"(a[1]), "r"(a[2]), "r"(a[3]), "r"(b[0]), "r"(b[1]));
}
__device__ __forceinline__ void ldsm_x4(uint32_t* r, uint32_t addr) {
    asm volatile("ldmatrix.sync.aligned.m8n8.x4.shared.b16 {%0,%1,%2,%3}, [%4];"
                 : "=r"(r[0]), "=r"(r[1]), "=r"(r[2]), "=r"(r[3]) : "r"(addr));
}
__device__ __forceinline__ void ldsm_x2(uint32_t* r, uint32_t addr) {
    asm volatile("ldmatrix.sync.aligned.m8n8.x2.shared.b16 {%0,%1}, [%2];"
                 : "=r"(r[0]), "=r"(r[1]) : "r"(addr));
}
__device__ __forceinline__ void conv_hi(__nv_bfloat16* hi, const float4& v) {
    const float* f = (const float*)&v;
    *(__nv_bfloat162*)(hi)     = __float22bfloat162_rn(make_float2(f[0], f[1]));
    *(__nv_bfloat162*)(hi + 2) = __float22bfloat162_rn(make_float2(f[2], f[3]));
}

__global__ __launch_bounds__(256, 1) void gemm_norm(const float* __restrict__ seq,
                                                    const float* __restrict__ Wm,
                                                    const float* __restrict__ bias) {
    extern __shared__ __align__(16) __nv_bfloat16 sm[];
    __shared__ float snn[4][GM];
    int t = threadIdx.x, wid = t >> 5, lane = t & 31;
    int wm = wid >> 2, wn = wid & 3;     // 2 x 4 warps, warp tile 64 x 32
    int m0 = blockIdx.y * GM, n0 = blockIdx.x * GN;
    int g = lane >> 2, tq = lane & 3;
    const bool do_dot = (blockIdx.x == 0);
    const float* zrow = g_z + blockIdx.y * Hh;   // m-block == batch

    const float* aptr[4];
    const float* bptr[4];
    int arow_[4], aq_[4];
    #pragma unroll
    for (int p = 0; p < 4; p++) {
        int j = t + p * 256;
        int row = j >> 3, qq = j & 7;
        arow_[p] = row; aq_[p] = qq;
        int r = m0 + row;
        aptr[p] = seq + ((size_t)(r >> 7) * Ss + g_off[r & 127]) * Hh + qq * 4;
        bptr[p] = Wm + (size_t)(n0 + row) * Hh + qq * 4;
    }
    int zq = (t & 7) * 4;   // z column base for this thread's qq

    // ldmatrix lane-offsets
    int lrow8 = lane & 7;
    int quad = lane >> 3;
    int aoff = ((quad & 1) * 8 + lrow8) * SP + (quad >> 1) * 8;
    int boff = lrow8 * SP + ((lane >> 3) & 1) * 8;
    uint32_t smem_u = (uint32_t)__cvta_generic_to_shared(sm);
    uint32_t a_base = smem_u + 2 * (AHI + (wm * 64) * SP + aoff);
    uint32_t b_base = smem_u + 2 * (BHI + (wn * 32) * SP + boff);

    float acc[4][4][4];
    #pragma unroll
    for (int mt = 0; mt < 4; mt++)
        #pragma unroll
        for (int nt = 0; nt < 4; nt++)
            #pragma unroll
            for (int e = 0; e < 4; e++) acc[mt][nt][e] = 0.f;
    float dacc[4] = {0.f, 0.f, 0.f, 0.f};

    float4 av[4], bv[4];
    #pragma unroll
    for (int p = 0; p < 4; p++) { av[p] = *(const float4*)aptr[p]; bv[p] = *(const float4*)bptr[p]; }
    if (do_dot) {
        float4 zv = *(const float4*)(zrow + zq);   // chunk 0
        #pragma unroll
        for (int p = 0; p < 4; p++)
            dacc[p] += av[p].x * zv.x + av[p].y * zv.y + av[p].z * zv.z + av[p].w * zv.w;
    }
    {
        __nv_bfloat16* sb = sm;
        #pragma unroll
        for (int p = 0; p < 4; p++) {
            int off = arow_[p] * SP + aq_[p] * 4;
            conv_hi(sb + AHI + off, av[p]);
            conv_hi(sb + BHI + off, bv[p]);
        }
    }
    __syncthreads();

    for (int c = 0; c < NC; c++) {
        if (c + 1 < NC) {
            #pragma unroll
            for (int p = 0; p < 4; p++) {
                av[p] = *(const float4*)(aptr[p] + (c + 1) * GK);
                bv[p] = *(const float4*)(bptr[p] + (c + 1) * GK);
            }
            if (do_dot) {
                float4 zv = *(const float4*)(zrow + (c + 1) * GK + zq);
                #pragma unroll
                for (int p = 0; p < 4; p++)
                    dacc[p] += av[p].x * zv.x + av[p].y * zv.y + av[p].z * zv.z + av[p].w * zv.w;
            }
        }
        uint32_t bufb = (c & 1) * (BUFS * 2);
        #pragma unroll
        for (int ks = 0; ks < 2; ks++) {
            uint32_t kbyte = bufb + ks * 32;
            uint32_t bfr[4][2];
            #pragma unroll
            for (int nt = 0; nt < 4; nt++)
                ldsm_x2(bfr[nt], b_base + kbyte + nt * (8 * SP * 2));
            #pragma unroll
            for (int mt = 0; mt < 4; mt++) {
                uint32_t afr[4];
                ldsm_x4(afr, a_base + kbyte + mt * (16 * SP * 2));
                #pragma unroll
                for (int nt = 0; nt < 4; nt++) mma16816(acc[mt][nt], afr, bfr[nt]);
            }
        }
        if (c + 1 < NC) {
            __nv_bfloat16* sw = sm + ((c + 1) & 1) * BUFS;
            #pragma unroll
            for (int p = 0; p < 4; p++) {
                int off = arow_[p] * SP + aq_[p] * 4;
                conv_hi(sw + AHI + off, av[p]);
                conv_hi(sw + BHI + off, bv[p]);
            }
        }
        __syncthreads();
    }

    // fused exact-dot reduction: 8 threads (same t>>3) share a row
    if (do_dot) {
        #pragma unroll
        for (int p = 0; p < 4; p++) {
            float d = dacc[p];
            d += __shfl_xor_sync(0xffffffffu, d, 1);
            d += __shfl_xor_sync(0xffffffffu, d, 2);
            d += __shfl_xor_sync(0xffffffffu, d, 4);
            if ((t & 7) == 0) g_dot[m0 + arow_[p]] = d;
        }
    }

    // epilogue: per-row ||y||^2 partials (y = acc + bias)
    float bb[4][2];
    #pragma unroll
    for (int nt = 0; nt < 4; nt++) {
        int gc = n0 + wn * 32 + nt * 8 + tq * 2;
        bb[nt][0] = bias[gc];
        bb[nt][1] = bias[gc + 1];
    }
    #pragma unroll
    for (int mt = 0; mt < 4; mt++) {
        #pragma unroll
        for (int h = 0; h < 2; h++) {
            float nr = 0.f;
            #pragma unroll
            for (int nt = 0; nt < 4; nt++) {
                float y0 = acc[mt][nt][2 * h]     + bb[nt][0];
                float y1 = acc[mt][nt][2 * h + 1] + bb[nt][1];
                nr += y0 * y0 + y1 * y1;
            }
            nr += __shfl_xor_sync(0xffffffffu, nr, 1);
            nr += __shfl_xor_sync(0xffffffffu, nr, 2);
            if (tq == 0) snn[wn][wm * 64 + mt * 16 + h * 8 + g] = nr;
        }
    }
    __syncthreads();
    if (t < GM)
        g_nnp[blockIdx.x][m0 + t] = snn[0][t] + snn[1][t] + snn[2][t] + snn[3][t];
}

// ---------------- kernel 5: combine + final loss (one block) ----------------
__global__ void combine_kernel(const int* __restrict__ labels, const int* __restrict__ events,
                               float* __restrict__ out) {
    __shared__ float s_num[64], s_den[64];
    __shared__ float s_xn[Bb], s_xb[Bb];
    int t = threadIdx.x;   // 1024 threads
    int w = t >> 5, lane = t & 31;
    if (t < Bb) {
        float X = 0.f, XB = 0.f;
        for (int p = 0; p < XPB; p++) { X += g_xnp[p][t]; XB += g_xbp[p][t]; }
        s_xn[t] = sqrtf(X);
        s_xb[t] = XB;
    }
    __syncthreads();
    float nums[2], dens[2];
    #pragma unroll
    for (int half = 0; half < 2; half++) {
        int r = t + half * 1024;
        int b = r >> 7;
        float nn = 0.f;
        #pragma unroll
        for (int p = 0; p < NBLK; p++) nn += g_nnp[p][r];
        float e = expf((g_dot[r] + s_xb[b]) / fmaxf(s_xn[b] * sqrtf(nn), 1e-8f));
        nums[half] = e * (float)labels[r];
        dens[half] = e * (float)events[r];
    }
    #pragma unroll
    for (int d = 16; d > 0; d >>= 1) {
        nums[0] += __shfl_xor_sync(0xffffffffu, nums[0], d);
        nums[1] += __shfl_xor_sync(0xffffffffu, nums[1], d);
        dens[0] += __shfl_xor_sync(0xffffffffu, dens[0], d);
        dens[1] += __shfl_xor_sync(0xffffffffu, dens[1], d);
    }
    if (lane == 0) {
        s_num[w]      = nums[0];  s_den[w]      = dens[0];
        s_num[32 + w] = nums[1];  s_den[32 + w] = dens[1];
    }
    __syncthreads();
    if (t < 32) {
        float loss = 0.f;
        if (t < 16) {
            int base = (t < 8) ? 4 * t : 32 + 4 * (t - 8);
            float num = s_num[base] + s_num[base + 1] + s_num[base + 2] + s_num[base + 3];
            float den = s_den[base] + s_den[base + 1] + s_den[base + 2] + s_den[base + 3];
            loss = logf(den) - logf(num);
        }
        #pragma unroll
        for (int d = 16; d > 0; d >>= 1) loss += __shfl_xor_sync(0xffffffffu, loss, d);
        if (t == 0) out[0] = loss / (float)Bb;
    }
}

// ---------------- launcher: single stream, 5 kernels ----------------
extern "C" void kernel_launch(void* const* d_in, const int* in_sizes, int n_in,
                              void* d_out, int out_size) {
    const int*   ids    = (const int*)d_in[0];
    const float* q      = (const float*)d_in[1];
    const float* seq    = (const float*)d_in[2];
    const int*   events = (const int*)d_in[3];
    const int*   labels = (const int*)d_in[4];
    const int*   offs   = (const int*)d_in[5];
    const float* Wm     = (const float*)d_in[7];
    const float* bias   = (const float*)d_in[8];

    cudaFuncSetAttribute(gemm_norm, cudaFuncAttributeMaxDynamicSharedMemorySize, SMEM_BYTES);
    cudaFuncSetAttribute(xproj_kernel, cudaFuncAttributeMaxDynamicSharedMemorySize, 65536);
    cudaFuncSetAttribute(zcomp_kernel, cudaFuncAttributeMaxDynamicSharedMemorySize, 65536);

    prep_kernel<<<Bb + 1, 256>>>(ids, offs);
    xproj_kernel<<<XPB, 256, 65536>>>(q, Wm, bias);
    zcomp_kernel<<<64, 256, 65536>>>(Wm);
    gemm_norm<<<dim3(NBLK, Mm / GM), 256, SMEM_BYTES>>>(seq, Wm, bias);
    combine_kernel<<<1, 1024>>>(labels, events, (float*)d_out);
}

// round 15
// speedup vs baseline: 1.0022x; 1.0022x over previous
#include <cuda_runtime.h>
#include <cuda_bf16.h>
#include <cstdint>

#define MASK_ID 50264
#define Bb 16
#define Ss 2048
#define Hh 1024
#define Ll 128
#define Mm (Bb*Ll)      // 2048
#define NBLK 16         // GEMM column blocks (GN=64)
#define XPB 128         // xproj blocks

// ---------------- device scratch ----------------
__device__ int   g_maskpos[Bb];
__device__ int   g_off[Ll];
__device__ float g_x[Bb*Hh];
__device__ float g_xT[Hh*Bb];
__device__ float g_z[Bb*Hh];
__device__ float g_xnp[XPB][Bb];
__device__ float g_xbp[XPB][Bb];
__device__ float g_dot[Mm];
__device__ float g_nnp[NBLK][Mm];

// ---------------- kernel 1: prep (17 blocks): offsets + per-batch mask scan ----------------
__global__ void prep_kernel(const int* __restrict__ ids_w, const int* __restrict__ off_w) {
    __shared__ int s_flag;
    __shared__ int s_min[256];
    int blk = blockIdx.x, t = threadIdx.x;
    if (t == 0) s_flag = 0;
    __syncthreads();
    int nz = 0;
    for (int i = t; i < 2048; i += 256) nz |= ids_w[2 * i + 1];
    if (nz) atomicOr(&s_flag, 1);
    __syncthreads();
    const bool is64 = (s_flag == 0);
    if (blk == Bb) {
        if (t < Ll) g_off[t] = is64 ? (int)((const long long*)off_w)[t] : off_w[t];
        return;
    }
    int b = blk;
    const long long* ids64 = (const long long*)ids_w;
    int mi = 0x7fffffff;
    for (int s = t; s < Ss; s += 256) {
        long long v = is64 ? ids64[(size_t)b * Ss + s] : (long long)ids_w[b * Ss + s];
        if (v == MASK_ID && s < mi) mi = s;
    }
    s_min[t] = mi;
    __syncthreads();
    for (int w = 128; w > 0; w >>= 1) {
        if (t < w) s_min[t] = min(s_min[t], s_min[t + w]);
        __syncthreads();
    }
    if (t == 0) g_maskpos[b] = (s_min[0] == 0x7fffffff) ? 0 : s_min[0];
}

// ---------------- kernel 2: x projection, W read once (grid 128, 256 thr) ----------------
__global__ void xproj_kernel(const float* __restrict__ q, const float* __restrict__ Wm,
                             const float* __restrict__ bias) {
    extern __shared__ __align__(16) float sq[];      // 64 KB
    __shared__ float sxn[8][Bb], sxb[8][Bb];
    int oc = blockIdx.x, t = threadIdx.x, wid = t >> 5, lane = t & 31;
    #pragma unroll
    for (int i = 0; i < 16; i++) {
        int idx = t + i * 256;
        int b = idx >> 8, h4 = idx & 255;
        ((float4*)sq)[idx] = *(const float4*)(q + ((size_t)b * Ss + g_maskpos[b]) * Hh + h4 * 4);
    }
    __syncthreads();
    int o = oc * 8 + wid;
    const float* wr = Wm + (size_t)o * Hh;
    float acc[Bb];
    #pragma unroll
    for (int b = 0; b < Bb; b++) acc[b] = 0.f;
    #pragma unroll
    for (int j = 0; j < 8; j++) {
        int h0 = j * 128 + lane * 4;
        float4 w4 = *(const float4*)(wr + h0);
        #pragma unroll
        for (int b = 0; b < Bb; b++) {
            float4 qv = *(const float4*)(sq + b * Hh + h0);
            acc[b] += w4.x * qv.x + w4.y * qv.y + w4.z * qv.z + w4.w * qv.w;
        }
    }
    #pragma unroll
    for (int b = 0; b < Bb; b++)
        #pragma unroll
        for (int d = 16; d > 0; d >>= 1)
            acc[b] += __shfl_xor_sync(0xffffffffu, acc[b], d);
    if (lane == 0) {
        float bo = bias[o];
        #pragma unroll
        for (int b = 0; b < Bb; b++) {
            float v = acc[b] + bo;
            g_x[b * Hh + o] = v;
            g_xT[o * Bb + b] = v;
            sxn[wid][b] = v * v;
            sxb[wid][b] = v * bo;
        }
    }
    __syncthreads();
    if (t < Bb) {
        float xn = 0.f, xb = 0.f;
        #pragma unroll
        for (int w = 0; w < 8; w++) { xn += sxn[w][t]; xb += sxb[w][t]; }
        g_xnp[oc][t] = xn;
        g_xbp[oc][t] = xb;
    }
}

// ---------------- kernel 3: z = W^T x (grid 64, 256 thr) ----------------
__global__ void zcomp_kernel(const float* __restrict__ Wm) {
    extern __shared__ __align__(16) float sxT[];     // 64 KB
    __shared__ float spz[16][Bb][16];
    int t = threadIdx.x;
    int hl = t & 15, och = t >> 4;
    int h = blockIdx.x * 16 + hl;
    #pragma unroll
    for (int i = 0; i < 16; i++) {
        int idx = t + i * 256;
        ((float4*)sxT)[idx] = ((const float4*)g_xT)[idx];
    }
    __syncthreads();
    float acc[Bb];
    #pragma unroll
    for (int b = 0; b < Bb; b++) acc[b] = 0.f;
    const float* wp = Wm + (size_t)(och * 64) * Hh + h;
    #pragma unroll 4
    for (int oi = 0; oi < 64; oi++) {
        float w = wp[(size_t)oi * Hh];
        const float4* xv = (const float4*)(sxT + (och * 64 + oi) * Bb);
        float4 x0 = xv[0], x1 = xv[1], x2 = xv[2], x3 = xv[3];
        acc[0]  += x0.x * w;  acc[1]  += x0.y * w;  acc[2]  += x0.z * w;  acc[3]  += x0.w * w;
        acc[4]  += x1.x * w;  acc[5]  += x1.y * w;  acc[6]  += x1.z * w;  acc[7]  += x1.w * w;
        acc[8]  += x2.x * w;  acc[9]  += x2.y * w;  acc[10] += x2.z * w;  acc[11] += x2.w * w;
        acc[12] += x3.x * w;  acc[13] += x3.y * w;  acc[14] += x3.z * w;  acc[15] += x3.w * w;
    }
    #pragma unroll
    for (int b = 0; b < Bb; b++) spz[och][b][hl] = acc[b];
    __syncthreads();
    int b = t >> 4, hl2 = t & 15;
    float z = 0.f;
    #pragma unroll
    for (int c = 0; c < 16; c++) z += spz[c][b][hl2];
    g_z[b * Hh + blockIdx.x * 16 + hl2] = z;
}

// ---------------- kernel 4: per-row exact dot = a . z (grid 2048, 128 thr) ----------------
__global__ void dotk_kernel(const float* __restrict__ seq) {
    __shared__ float sred[4];
    int r = blockIdx.x, t = threadIdx.x;
    int b = r >> 7, l = r & 127;
    const float4* a4 = (const float4*)(seq + ((size_t)b * Ss + g_off[l]) * Hh);
    const float4* z4 = (const float4*)(g_z + b * Hh);
    float d = 0.f;
    #pragma unroll
    for (int i = t; i < Hh / 4; i += 128) {
        float4 av = a4[i], zv = z4[i];
        d += av.x * zv.x + av.y * zv.y + av.z * zv.z + av.w * zv.w;
    }
    #pragma unroll
    for (int s = 16; s > 0; s >>= 1) d += __shfl_xor_sync(0xffffffffu, d, s);
    int w = t >> 5;
    if ((t & 31) == 0) sred[w] = d;
    __syncthreads();
    if (t == 0) g_dot[r] = sred[0] + sred[1] + sred[2] + sred[3];
}

// ---------------- kernel 5: bf16 HMMA GEMM, 128x64 tiles, 2 CTAs/SM ----------------
#define GM 128
#define GN 64
#define GK 32
#define NC (Hh / GK)
#define SP 40
#define AHI 0
#define BHI (128*SP)
#define BUFS ((128+64)*SP)          // 7680 bf16 per buffer
#define SMEM_BYTES (2*BUFS*2)       // 30720 B

__device__ __forceinline__ void mma16816(float* d, const uint32_t* a, const uint32_t* b) {
    asm volatile("mma.sync.aligned.m16n8k16.row.col.f32.bf16.bf16.f32 "
                 "{%0,%1,%2,%3},{%4,%5,%6,%7},{%8,%9},{%0,%1,%2,%3};"
                 : "+f"(d[0]), "+f"(d[1]), "+f"(d[2]), "+f"(d[3])
                 : "r"(a[0]), "r"(a[1]), "r"(a[2]), "r"(a[3]), "r"(b[0]), "r"(b[1]));
}
__device__ __forceinline__ void ldsm_x4(uint32_t* r, uint32_t addr) {
    asm volatile("ldmatrix.sync.aligned.m8n8.x4.shared.b16 {%0,%1,%2,%3}, [%4];"
                 : "=r"(r[0]), "=r"(r[1]), "=r"(r[2]), "=r"(r[3]) : "r"(addr));
}
__device__ __forceinline__ void ldsm_x2(uint32_t* r, uint32_t addr) {
    asm volatile("ldmatrix.sync.aligned.m8n8.x2.shared.b16 {%0,%1}, [%2];"
                 : "=r"(r[0]), "=r"(r[1]) : "r"(addr));
}
__device__ __forceinline__ void conv_hi(__nv_bfloat16* hi, const float4& v) {
    const float* f = (const float*)&v;
    *(__nv_bfloat162*)(hi)     = __float22bfloat162_rn(make_float2(f[0], f[1]));
    *(__nv_bfloat162*)(hi + 2) = __float22bfloat162_rn(make_float2(f[2], f[3]));
}

__global__ __launch_bounds__(256, 2) void gemm_norm(const float* __restrict__ seq,
                                                    const float* __restrict__ Wm,
                                                    const float* __restrict__ bias) {
    extern __shared__ __align__(16) __nv_bfloat16 sm[];
    __shared__ float snn[4][GM];
    int t = threadIdx.x, wid = t >> 5, lane = t & 31;
    int wm = wid >> 2, wn = wid & 3;     // 2 x 4 warps, warp tile 64 x 16
    int m0 = blockIdx.y * GM, n0 = blockIdx.x * GN;
    int g = lane >> 2, tq = lane & 3;

    // A loaders: 4 float4/thread; B loaders: 2 float4/thread
    const float* aptr[4];
    int arow_[4], aq_[4];
    #pragma unroll
    for (int p = 0; p < 4; p++) {
        int j = t + p * 256;
        int row = j >> 3, qq = j & 7;
        arow_[p] = row; aq_[p] = qq;
        int r = m0 + row;
        aptr[p] = seq + ((size_t)(r >> 7) * Ss + g_off[r & 127]) * Hh + qq * 4;
    }
    const float* bptr[2];
    int brow_[2], bq_[2];
    #pragma unroll
    for (int p = 0; p < 2; p++) {
        int j = t + p * 256;
        int row = j >> 3, qq = j & 7;
        brow_[p] = row; bq_[p] = qq;
        bptr[p] = Wm + (size_t)(n0 + row) * Hh + qq * 4;
    }

    // ldmatrix lane-offsets
    int lrow8 = lane & 7;
    int quad = lane >> 3;
    int aoff = ((quad & 1) * 8 + lrow8) * SP + (quad >> 1) * 8;
    int boff = lrow8 * SP + ((lane >> 3) & 1) * 8;
    uint32_t smem_u = (uint32_t)__cvta_generic_to_shared(sm);
    uint32_t a_base = smem_u + 2 * (AHI + (wm * 64) * SP + aoff);
    uint32_t b_base = smem_u + 2 * (BHI + (wn * 16) * SP + boff);

    float acc[4][2][4];
    #pragma unroll
    for (int mt = 0; mt < 4; mt++)
        #pragma unroll
        for (int nt = 0; nt < 2; nt++)
            #pragma unroll
            for (int e = 0; e < 4; e++) acc[mt][nt][e] = 0.f;

    float4 av[4], bv[2];
    #pragma unroll
    for (int p = 0; p < 4; p++) av[p] = *(const float4*)aptr[p];
    #pragma unroll
    for (int p = 0; p < 2; p++) bv[p] = *(const float4*)bptr[p];
    {
        __nv_bfloat16* sb = sm;
        #pragma unroll
        for (int p = 0; p < 4; p++)
            conv_hi(sb + AHI + arow_[p] * SP + aq_[p] * 4, av[p]);
        #pragma unroll
        for (int p = 0; p < 2; p++)
            conv_hi(sb + BHI + brow_[p] * SP + bq_[p] * 4, bv[p]);
    }
    __syncthreads();

    for (int c = 0; c < NC; c++) {
        if (c + 1 < NC) {
            #pragma unroll
            for (int p = 0; p < 4; p++) av[p] = *(const float4*)(aptr[p] + (c + 1) * GK);
            #pragma unroll
            for (int p = 0; p < 2; p++) bv[p] = *(const float4*)(bptr[p] + (c + 1) * GK);
        }
        uint32_t bufb = (c & 1) * (BUFS * 2);
        #pragma unroll
        for (int ks = 0; ks < 2; ks++) {
            uint32_t kbyte = bufb + ks * 32;
            uint32_t bfr[2][2];
            #pragma unroll
            for (int nt = 0; nt < 2; nt++)
                ldsm_x2(bfr[nt], b_base + kbyte + nt * (8 * SP * 2));
            #pragma unroll
            for (int mt = 0; mt < 4; mt++) {
                uint32_t afr[4];
                ldsm_x4(afr, a_base + kbyte + mt * (16 * SP * 2));
                #pragma unroll
                for (int nt = 0; nt < 2; nt++) mma16816(acc[mt][nt], afr, bfr[nt]);
            }
        }
        if (c + 1 < NC) {
            __nv_bfloat16* sw = sm + ((c + 1) & 1) * BUFS;
            #pragma unroll
            for (int p = 0; p < 4; p++)
                conv_hi(sw + AHI + arow_[p] * SP + aq_[p] * 4, av[p]);
            #pragma unroll
            for (int p = 0; p < 2; p++)
                conv_hi(sw + BHI + brow_[p] * SP + bq_[p] * 4, bv[p]);
        }
        __syncthreads();
    }

    // epilogue: per-row ||y||^2 partials over this CTA's 64 cols (y = acc + bias)
    float bb[2][2];
    #pragma unroll
    for (int nt = 0; nt < 2; nt++) {
        int gc = n0 + wn * 16 + nt * 8 + tq * 2;
        bb[nt][0] = bias[gc];
        bb[nt][1] = bias[gc + 1];
    }
    #pragma unroll
    for (int mt = 0; mt < 4; mt++) {
        #pragma unroll
        for (int h = 0; h < 2; h++) {
            float nr = 0.f;
            #pragma unroll
            for (int nt = 0; nt < 2; nt++) {
                float y0 = acc[mt][nt][2 * h]     + bb[nt][0];
                float y1 = acc[mt][nt][2 * h + 1] + bb[nt][1];
                nr += y0 * y0 + y1 * y1;
            }
            nr += __shfl_xor_sync(0xffffffffu, nr, 1);
            nr += __shfl_xor_sync(0xffffffffu, nr, 2);
            if (tq == 0) snn[wn][wm * 64 + mt * 16 + h * 8 + g] = nr;
        }
    }
    __syncthreads();
    if (t < GM)
        g_nnp[blockIdx.x][m0 + t] = snn[0][t] + snn[1][t] + snn[2][t] + snn[3][t];
}

// ---------------- kernel 6: combine + final loss (one block) ----------------
__global__ void combine_kernel(const int* __restrict__ labels, const int* __restrict__ events,
                               float* __restrict__ out) {
    __shared__ float s_num[64], s_den[64];
    __shared__ float s_xn[Bb], s_xb[Bb];
    int t = threadIdx.x;   // 1024 threads
    int w = t >> 5, lane = t & 31;
    if (t < Bb) {
        float X = 0.f, XB = 0.f;
        for (int p = 0; p < XPB; p++) { X += g_xnp[p][t]; XB += g_xbp[p][t]; }
        s_xn[t] = sqrtf(X);
        s_xb[t] = XB;
    }
    __syncthreads();
    float nums[2], dens[2];
    #pragma unroll
    for (int half = 0; half < 2; half++) {
        int r = t + half * 1024;
        int b = r >> 7;
        float nn = 0.f;
        #pragma unroll
        for (int p = 0; p < NBLK; p++) nn += g_nnp[p][r];
        float e = expf((g_dot[r] + s_xb[b]) / fmaxf(s_xn[b] * sqrtf(nn), 1e-8f));
        nums[half] = e * (float)labels[r];
        dens[half] = e * (float)events[r];
    }
    #pragma unroll
    for (int d = 16; d > 0; d >>= 1) {
        nums[0] += __shfl_xor_sync(0xffffffffu, nums[0], d);
        nums[1] += __shfl_xor_sync(0xffffffffu, nums[1], d);
        dens[0] += __shfl_xor_sync(0xffffffffu, dens[0], d);
        dens[1] += __shfl_xor_sync(0xffffffffu, dens[1], d);
    }
    if (lane == 0) {
        s_num[w]      = nums[0];  s_den[w]      = dens[0];
        s_num[32 + w] = nums[1];  s_den[32 + w] = dens[1];
    }
    __syncthreads();
    if (t < 32) {
        float loss = 0.f;
        if (t < 16) {
            int base = (t < 8) ? 4 * t : 32 + 4 * (t - 8);
            float num = s_num[base] + s_num[base + 1] + s_num[base + 2] + s_num[base + 3];
            float den = s_den[base] + s_den[base + 1] + s_den[base + 2] + s_den[base + 3];
            loss = logf(den) - logf(num);
        }
        #pragma unroll
        for (int d = 16; d > 0; d >>= 1) loss += __shfl_xor_sync(0xffffffffu, loss, d);
        if (t == 0) out[0] = loss / (float)Bb;
    }
}

// ---------------- launcher: single stream ----------------
extern "C" void kernel_launch(void* const* d_in, const int* in_sizes, int n_in,
                              void* d_out, int out_size) {
    const int*   ids    = (const int*)d_in[0];
    const float* q      = (const float*)d_in[1];
    const float* seq    = (const float*)d_in[2];
    const int*   events = (const int*)d_in[3];
    const int*   labels = (const int*)d_in[4];
    const int*   offs   = (const int*)d_in[5];
    const float* Wm     = (const float*)d_in[7];
    const float* bias   = (const float*)d_in[8];

    cudaFuncSetAttribute(gemm_norm, cudaFuncAttributeMaxDynamicSharedMemorySize, SMEM_BYTES);
    cudaFuncSetAttribute(xproj_kernel, cudaFuncAttributeMaxDynamicSharedMemorySize, 65536);
    cudaFuncSetAttribute(zcomp_kernel, cudaFuncAttributeMaxDynamicSharedMemorySize, 65536);

    prep_kernel<<<Bb + 1, 256>>>(ids, offs);
    xproj_kernel<<<XPB, 256, 65536>>>(q, Wm, bias);
    zcomp_kernel<<<64, 256, 65536>>>(Wm);
    dotk_kernel<<<Mm, 128>>>(seq);
    gemm_norm<<<dim3(NBLK, Mm / GM), 256, SMEM_BYTES>>>(seq, Wm, bias);
    combine_kernel<<<1, 1024>>>(labels, events, (float*)d_out);
}

// round 17
// speedup vs baseline: 1.4677x; 1.4645x over previous
#include <cuda_runtime.h>
#include <cuda_bf16.h>
#include <cstdint>

#define MASK_ID 50264
#define Bb 16
#define Ss 2048
#define Hh 1024
#define Ll 128
#define Mm (Bb*Ll)      // 2048
#define NBLK 8          // GEMM column blocks
#define XPB 128         // xproj blocks

// ---------------- device scratch ----------------
__device__ int   g_maskpos[Bb];
__device__ int   g_off[Ll];
__device__ float g_x[Bb*Hh];
__device__ float g_xT[Hh*Bb];
__device__ float g_z[Bb*Hh];
__device__ float g_xnp[XPB][Bb];
__device__ float g_xbp[XPB][Bb];
__device__ float g_dot[Mm];
__device__ float g_nnp[NBLK][Mm];
__device__ __nv_bfloat16 g_Abf[(size_t)Mm*Hh];   // 4 MB gathered A (bf16)
__device__ __nv_bfloat16 g_Wbf[(size_t)Hh*Hh];   // 2 MB W (bf16)

// ---------------- kernel 1: prep ----------------
__global__ void prep_kernel(const int* __restrict__ ids_w, const int* __restrict__ off_w) {
    __shared__ int s_flag;
    __shared__ int s_min[256];
    int blk = blockIdx.x, t = threadIdx.x;
    if (t == 0) s_flag = 0;
    __syncthreads();
    int nz = 0;
    for (int i = t; i < 2048; i += 256) nz |= ids_w[2 * i + 1];
    if (nz) atomicOr(&s_flag, 1);
    __syncthreads();
    const bool is64 = (s_flag == 0);
    if (blk == Bb) {
        if (t < Ll) g_off[t] = is64 ? (int)((const long long*)off_w)[t] : off_w[t];
        return;
    }
    int b = blk;
    const long long* ids64 = (const long long*)ids_w;
    int mi = 0x7fffffff;
    for (int s = t; s < Ss; s += 256) {
        long long v = is64 ? ids64[(size_t)b * Ss + s] : (long long)ids_w[b * Ss + s];
        if (v == MASK_ID && s < mi) mi = s;
    }
    s_min[t] = mi;
    __syncthreads();
    for (int w = 128; w > 0; w >>= 1) {
        if (t < w) s_min[t] = min(s_min[t], s_min[t + w]);
        __syncthreads();
    }
    if (t == 0) g_maskpos[b] = (s_min[0] == 0x7fffffff) ? 0 : s_min[0];
}

// ---------------- kernel 2: gather + f32->bf16 convert ----------------
__global__ void conv_kernel(const float* __restrict__ seq, const float* __restrict__ Wm) {
    int row = blockIdx.x, t = threadIdx.x;   // 3072 blocks, 256 thr
    const float* src;
    __nv_bfloat16* dst;
    if (row < Mm) {
        int b = row >> 7, l = row & 127;
        src = seq + ((size_t)b * Ss + g_off[l]) * Hh;
        dst = g_Abf + (size_t)row * Hh;
    } else {
        src = Wm + (size_t)(row - Mm) * Hh;
        dst = g_Wbf + (size_t)(row - Mm) * Hh;
    }
    float4 v = *(const float4*)(src + t * 4);
    *(__nv_bfloat162*)(dst + t * 4)     = __float22bfloat162_rn(make_float2(v.x, v.y));
    *(__nv_bfloat162*)(dst + t * 4 + 2) = __float22bfloat162_rn(make_float2(v.z, v.w));
}

// ---------------- kernel 3: x projection (grid 128, 256 thr) ----------------
__global__ void xproj_kernel(const float* __restrict__ q, const float* __restrict__ Wm,
                             const float* __restrict__ bias) {
    extern __shared__ __align__(16) float sq[];      // 64 KB
    __shared__ float sxn[8][Bb], sxb[8][Bb];
    int oc = blockIdx.x, t = threadIdx.x, wid = t >> 5, lane = t & 31;
    #pragma unroll
    for (int i = 0; i < 16; i++) {
        int idx = t + i * 256;
        int b = idx >> 8, h4 = idx & 255;
        ((float4*)sq)[idx] = *(const float4*)(q + ((size_t)b * Ss + g_maskpos[b]) * Hh + h4 * 4);
    }
    __syncthreads();
    int o = oc * 8 + wid;
    const float* wr = Wm + (size_t)o * Hh;
    float acc[Bb];
    #pragma unroll
    for (int b = 0; b < Bb; b++) acc[b] = 0.f;
    #pragma unroll
    for (int j = 0; j < 8; j++) {
        int h0 = j * 128 + lane * 4;
        float4 w4 = *(const float4*)(wr + h0);
        #pragma unroll
        for (int b = 0; b < Bb; b++) {
            float4 qv = *(const float4*)(sq + b * Hh + h0);
            acc[b] += w4.x * qv.x + w4.y * qv.y + w4.z * qv.z + w4.w * qv.w;
        }
    }
    #pragma unroll
    for (int b = 0; b < Bb; b++)
        #pragma unroll
        for (int d = 16; d > 0; d >>= 1)
            acc[b] += __shfl_xor_sync(0xffffffffu, acc[b], d);
    if (lane == 0) {
        float bo = bias[o];
        #pragma unroll
        for (int b = 0; b < Bb; b++) {
            float v = acc[b] + bo;
            g_x[b * Hh + o] = v;
            g_xT[o * Bb + b] = v;
            sxn[wid][b] = v * v;
            sxb[wid][b] = v * bo;
        }
    }
    __syncthreads();
    if (t < Bb) {
        float xn = 0.f, xb = 0.f;
        #pragma unroll
        for (int w = 0; w < 8; w++) { xn += sxn[w][t]; xb += sxb[w][t]; }
        g_xnp[oc][t] = xn;
        g_xbp[oc][t] = xb;
    }
}

// ---------------- kernel 4: z = W^T x (grid 64, 256 thr) ----------------
__global__ void zcomp_kernel(const float* __restrict__ Wm) {
    extern __shared__ __align__(16) float sxT[];     // 64 KB
    __shared__ float spz[16][Bb][16];
    int t = threadIdx.x;
    int hl = t & 15, och = t >> 4;
    int h = blockIdx.x * 16 + hl;
    #pragma unroll
    for (int i = 0; i < 16; i++) {
        int idx = t + i * 256;
        ((float4*)sxT)[idx] = ((const float4*)g_xT)[idx];
    }
    __syncthreads();
    float acc[Bb];
    #pragma unroll
    for (int b = 0; b < Bb; b++) acc[b] = 0.f;
    const float* wp = Wm + (size_t)(och * 64) * Hh + h;
    #pragma unroll 4
    for (int oi = 0; oi < 64; oi++) {
        float w = wp[(size_t)oi * Hh];
        const float4* xv = (const float4*)(sxT + (och * 64 + oi) * Bb);
        float4 x0 = xv[0], x1 = xv[1], x2 = xv[2], x3 = xv[3];
        acc[0]  += x0.x * w;  acc[1]  += x0.y * w;  acc[2]  += x0.z * w;  acc[3]  += x0.w * w;
        acc[4]  += x1.x * w;  acc[5]  += x1.y * w;  acc[6]  += x1.z * w;  acc[7]  += x1.w * w;
        acc[8]  += x2.x * w;  acc[9]  += x2.y * w;  acc[10] += x2.z * w;  acc[11] += x2.w * w;
        acc[12] += x3.x * w;  acc[13] += x3.y * w;  acc[14] += x3.z * w;  acc[15] += x3.w * w;
    }
    #pragma unroll
    for (int b = 0; b < Bb; b++) spz[och][b][hl] = acc[b];
    __syncthreads();
    int b = t >> 4, hl2 = t & 15;
    float z = 0.f;
    #pragma unroll
    for (int c = 0; c < 16; c++) z += spz[c][b][hl2];
    g_z[b * Hh + blockIdx.x * 16 + hl2] = z;
}

// ---------------- kernel 5: per-row exact dot = a . z (grid 2048, 128 thr) ----------------
__global__ void dotk_kernel(const float* __restrict__ seq) {
    __shared__ float sred[4];
    int r = blockIdx.x, t = threadIdx.x;
    int b = r >> 7, l = r & 127;
    const float4* a4 = (const float4*)(seq + ((size_t)b * Ss + g_off[l]) * Hh);
    const float4* z4 = (const float4*)(g_z + b * Hh);
    float d = 0.f;
    #pragma unroll
    for (int i = t; i < Hh / 4; i += 128) {
        float4 av = a4[i], zv = z4[i];
        d += av.x * zv.x + av.y * zv.y + av.z * zv.z + av.w * zv.w;
    }
    #pragma unroll
    for (int s = 16; s > 0; s >>= 1) d += __shfl_xor_sync(0xffffffffu, d, s);
    int w = t >> 5;
    if ((t & 31) == 0) sred[w] = d;
    __syncthreads();
    if (t == 0) g_dot[r] = sred[0] + sred[1] + sred[2] + sred[3];
}

// ---------------- kernel 6: cp.async 4-stage bf16 HMMA GEMM ----------------
#define GM 128
#define GN 128
#define GK 32
#define NC (Hh / GK)    // 32
#define NSTAGE 4
#define SP 40
#define AHI 0
#define BHI (128*SP)
#define BUFS (256*SP)                  // bf16 per stage (10240)
#define SMEM_BYTES (NSTAGE*BUFS*2)     // 81920 B

__device__ __forceinline__ void mma16816(float* d, const uint32_t* a, const uint32_t* b) {
    asm volatile("mma.sync.aligned.m16n8k16.row.col.f32.bf16.bf16.f32 "
                 "{%0,%1,%2,%3},{%4,%5,%6,%7},{%8,%9},{%0,%1,%2,%3};"
                 : "+f"(d[0]), "+f"(d[1]), "+f"(d[2]), "+f"(d[3])
                 : "r"(a[0]), "r"(a[1]), "r"(a[2]), "r"(a[3]), "r"(b[0]), "r"(b[1]));
}
__device__ __forceinline__ void ldsm_x4(uint32_t* r, uint32_t addr) {
    asm volatile("ldmatrix.sync.aligned.m8n8.x4.shared.b16 {%0,%1,%2,%3}, [%4];"
                 : "=r"(r[0]), "=r"(r[1]), "=r"(r[2]), "=r"(r[3]) : "r"(addr));
}
__device__ __forceinline__ void ldsm_x2(uint32_t* r, uint32_t addr) {
    asm volatile("ldmatrix.sync.aligned.m8n8.x2.shared.b16 {%0,%1}, [%2];"
                 : "=r"(r[0]), "=r"(r[1]) : "r"(addr));
}
__device__ __forceinline__ void cp16(uint32_t dst, const void* src) {
    asm volatile("cp.async.cg.shared.global [%0], [%1], 16;" :: "r"(dst), "l"(src) : "memory");
}

__global__ __launch_bounds__(256, 1) void gemm_norm(const float* __restrict__ bias) {
    extern __shared__ __align__(16) __nv_bfloat16 sm[];
    __shared__ float snn[4][GM];
    int t = threadIdx.x, wid = t >> 5, lane = t & 31;
    int wm = wid >> 2, wn = wid & 3;     // 2 x 4 warps, warp tile 64 x 32
    int m0 = blockIdx.y * GM, n0 = blockIdx.x * GN;
    int g = lane >> 2, tq = lane & 3;
    uint32_t smem_u = (uint32_t)__cvta_generic_to_shared(sm);

    // loaders: per stage each thread cp.asyncs 2 x 16B of A and 2 x 16B of B
    const __nv_bfloat16* asrc[2];
    const __nv_bfloat16* bsrc[2];
    uint32_t adst[2], bdst[2];
    #pragma unroll
    for (int p = 0; p < 2; p++) {
        int idx = t + p * 256;
        int row = idx >> 2, seg = idx & 3;
        asrc[p] = g_Abf + (size_t)(m0 + row) * Hh + seg * 8;
        bsrc[p] = g_Wbf + (size_t)(n0 + row) * Hh + seg * 8;
        adst[p] = smem_u + 2 * (AHI + row * SP + seg * 8);
        bdst[p] = smem_u + 2 * (BHI + row * SP + seg * 8);
    }

    // ldmatrix lane-offsets
    int lrow8 = lane & 7;
    int quad = lane >> 3;
    int aoff = ((quad & 1) * 8 + lrow8) * SP + (quad >> 1) * 8;
    int boff = lrow8 * SP + ((lane >> 3) & 1) * 8;
    uint32_t a_base = smem_u + 2 * (AHI + (wm * 64) * SP + aoff);
    uint32_t b_base = smem_u + 2 * (BHI + (wn * 32) * SP + boff);

    float acc[4][4][4];
    #pragma unroll
    for (int mt = 0; mt < 4; mt++)
        #pragma unroll
        for (int nt = 0; nt < 4; nt++)
            #pragma unroll
            for (int e = 0; e < 4; e++) acc[mt][nt][e] = 0.f;

    // prologue: issue stages 0..NSTAGE-2
    #pragma unroll
    for (int s = 0; s < NSTAGE - 1; s++) {
        uint32_t so = (uint32_t)(s * BUFS * 2);
        #pragma unroll
        for (int p = 0; p < 2; p++) {
            cp16(adst[p] + so, asrc[p] + s * GK);
            cp16(bdst[p] + so, bsrc[p] + s * GK);
        }
        asm volatile("cp.async.commit_group;" ::: "memory");
    }

    for (int c = 0; c < NC; c++) {
        asm volatile("cp.async.wait_group %0;" :: "n"(NSTAGE - 2) : "memory");
        __syncthreads();
        uint32_t bufb = (uint32_t)((c % NSTAGE) * BUFS * 2);
        #pragma unroll
        for (int ks = 0; ks < 2; ks++) {
            uint32_t kbyte = bufb + ks * 32;
            uint32_t bfr[4][2];
            #pragma unroll
            for (int nt = 0; nt < 4; nt++)
                ldsm_x2(bfr[nt], b_base + kbyte + nt * (8 * SP * 2));
            #pragma unroll
            for (int mt = 0; mt < 4; mt++) {
                uint32_t afr[4];
                ldsm_x4(afr, a_base + kbyte + mt * (16 * SP * 2));
                #pragma unroll
                for (int nt = 0; nt < 4; nt++) mma16816(acc[mt][nt], afr, bfr[nt]);
            }
        }
        int cn = c + NSTAGE - 1;
        if (cn < NC) {
            uint32_t so = (uint32_t)((cn % NSTAGE) * BUFS * 2);
            #pragma unroll
            for (int p = 0; p < 2; p++) {
                cp16(adst[p] + so, asrc[p] + cn * GK);
                cp16(bdst[p] + so, bsrc[p] + cn * GK);
            }
        }
        asm volatile("cp.async.commit_group;" ::: "memory");
    }
    asm volatile("cp.async.wait_group 0;" ::: "memory");

    // epilogue: per-row ||y||^2 partials (y = acc + bias)
    float bb[4][2];
    #pragma unroll
    for (int nt = 0; nt < 4; nt++) {
        int gc = n0 + wn * 32 + nt * 8 + tq * 2;
        bb[nt][0] = bias[gc];
        bb[nt][1] = bias[gc + 1];
    }
    #pragma unroll
    for (int mt = 0; mt < 4; mt++) {
        #pragma unroll
        for (int h = 0; h < 2; h++) {
            float nr = 0.f;
            #pragma unroll
            for (int nt = 0; nt < 4; nt++) {
                float y0 = acc[mt][nt][2 * h]     + bb[nt][0];
                float y1 = acc[mt][nt][2 * h + 1] + bb[nt][1];
                nr += y0 * y0 + y1 * y1;
            }
            nr += __shfl_xor_sync(0xffffffffu, nr, 1);
            nr += __shfl_xor_sync(0xffffffffu, nr, 2);
            if (tq == 0) snn[wn][wm * 64 + mt * 16 + h * 8 + g] = nr;
        }
    }
    __syncthreads();
    if (t < GM)
        g_nnp[blockIdx.x][m0 + t] = snn[0][t] + snn[1][t] + snn[2][t] + snn[3][t];
}

// ---------------- kernel 7: combine + final loss ----------------
__global__ void combine_kernel(const int* __restrict__ labels, const int* __restrict__ events,
                               float* __restrict__ out) {
    __shared__ float s_num[64], s_den[64];
    __shared__ float s_xn[Bb], s_xb[Bb];
    int t = threadIdx.x;   // 1024 threads
    int w = t >> 5, lane = t & 31;
    if (t < Bb) {
        float X = 0.f, XB = 0.f;
        for (int p = 0; p < XPB; p++) { X += g_xnp[p][t]; XB += g_xbp[p][t]; }
        s_xn[t] = sqrtf(X);
        s_xb[t] = XB;
    }
    __syncthreads();
    float nums[2], dens[2];
    #pragma unroll
    for (int half = 0; half < 2; half++) {
        int r = t + half * 1024;
        int b = r >> 7;
        float nn = 0.f;
        #pragma unroll
        for (int p = 0; p < NBLK; p++) nn += g_nnp[p][r];
        float e = expf((g_dot[r] + s_xb[b]) / fmaxf(s_xn[b] * sqrtf(nn), 1e-8f));
        nums[half] = e * (float)labels[r];
        dens[half] = e * (float)events[r];
    }
    #pragma unroll
    for (int d = 16; d > 0; d >>= 1) {
        nums[0] += __shfl_xor_sync(0xffffffffu, nums[0], d);
        nums[1] += __shfl_xor_sync(0xffffffffu, nums[1], d);
        dens[0] += __shfl_xor_sync(0xffffffffu, dens[0], d);
        dens[1] += __shfl_xor_sync(0xffffffffu, dens[1], d);
    }
    if (lane == 0) {
        s_num[w]      = nums[0];  s_den[w]      = dens[0];
        s_num[32 + w] = nums[1];  s_den[32 + w] = dens[1];
    }
    __syncthreads();
    if (t < 32) {
        float loss = 0.f;
        if (t < 16) {
            int base = (t < 8) ? 4 * t : 32 + 4 * (t - 8);
            float num = s_num[base] + s_num[base + 1] + s_num[base + 2] + s_num[base + 3];
            float den = s_den[base] + s_den[base + 1] + s_den[base + 2] + s_den[base + 3];
            loss = logf(den) - logf(num);
        }
        #pragma unroll
        for (int d = 16; d > 0; d >>= 1) loss += __shfl_xor_sync(0xffffffffu, loss, d);
        if (t == 0) out[0] = loss / (float)Bb;
    }
}

// ---------------- launcher: two-stream overlap ----------------
extern "C" void kernel_launch(void* const* d_in, const int* in_sizes, int n_in,
                              void* d_out, int out_size) {
    const int*   ids    = (const int*)d_in[0];
    const float* q      = (const float*)d_in[1];
    const float* seq    = (const float*)d_in[2];
    const int*   events = (const int*)d_in[3];
    const int*   labels = (const int*)d_in[4];
    const int*   offs   = (const int*)d_in[5];
    const float* Wm     = (const float*)d_in[7];
    const float* bias   = (const float*)d_in[8];

    cudaFuncSetAttribute(gemm_norm, cudaFuncAttributeMaxDynamicSharedMemorySize, SMEM_BYTES);
    cudaFuncSetAttribute(xproj_kernel, cudaFuncAttributeMaxDynamicSharedMemorySize, 65536);
    cudaFuncSetAttribute(zcomp_kernel, cudaFuncAttributeMaxDynamicSharedMemorySize, 65536);

    cudaStream_t s2;
    cudaStreamCreateWithFlags(&s2, cudaStreamNonBlocking);
    cudaEvent_t ef, ej;
    cudaEventCreateWithFlags(&ef, cudaEventDisableTiming);
    cudaEventCreateWithFlags(&ej, cudaEventDisableTiming);

    prep_kernel<<<Bb + 1, 256>>>(ids, offs);
    cudaEventRecord(ef, 0);
    cudaStreamWaitEvent(s2, ef, 0);

    // side chain (s2): exact dot path, overlaps with conv+gemm
    xproj_kernel<<<XPB, 256, 65536, s2>>>(q, Wm, bias);
    zcomp_kernel<<<64, 256, 65536, s2>>>(Wm);
    dotk_kernel<<<Mm, 128, 0, s2>>>(seq);
    cudaEventRecord(ej, s2);

    // main chain: convert once, then deep-pipelined GEMM
    conv_kernel<<<Mm + Hh, 256>>>(seq, Wm);
    gemm_norm<<<dim3(NBLK, Mm / GM), 256, SMEM_BYTES>>>(bias);

    cudaStreamWaitEvent(0, ej, 0);
    combine_kernel<<<1, 1024>>>(labels, events, (float*)d_out);
}